// round 9
// baseline (speedup 1.0000x reference)
#include <cuda_runtime.h>
#include <cuda_fp16.h>
#include <cstdint>

#define NN    40000
#define DH    128
#define DOUT  64
#define EMAX  700000
#define NB    157           // ceil(40000/256)

// ---------------- scratch (device globals; no allocation allowed) ----------------
__device__ __align__(16) float  g_dinv[NN];
__device__ __align__(16) __half g_hs1h[NN * DH];   // fp16 h1 = x@W1 (UNSCALED)
__device__ __align__(16) float  g_h1r [NN * DH];   // relu(layer1 out), fp32
__device__ __align__(16) __half g_hs2h[NN * DOUT]; // fp16 dinv-prescaled h2
__device__ int g_cnt [NN];
__device__ int g_off [NN + 1];
__device__ int g_fill[NN];
__device__ int g_csr_src[EMAX];
__device__ int g_bsum[NB];
__device__ int g_is64;

__device__ __forceinline__ void mma_f16(float4& c, uint32_t a0, uint32_t a1,
                                        uint32_t a2, uint32_t a3,
                                        uint32_t b0, uint32_t b1) {
    asm volatile("mma.sync.aligned.m16n8k16.row.col.f32.f16.f16.f32 "
                 "{%0,%1,%2,%3}, {%4,%5,%6,%7}, {%8,%9}, {%0,%1,%2,%3};"
                 : "+f"(c.x), "+f"(c.y), "+f"(c.z), "+f"(c.w)
                 : "r"(a0), "r"(a1), "r"(a2), "r"(a3), "r"(b0), "r"(b1));
}

// ---------------- init: zero counts, detect edge width ----------------
__global__ void k_init(const int* __restrict__ ei32) {
    int i = blockIdx.x * blockDim.x + threadIdx.x;
    if (i < NN) g_cnt[i] = 0;
    if (i == 0) {
        int zeros = 0;
        #pragma unroll
        for (int j = 1; j < 128; j += 2) zeros += (ei32[j] == 0);
        g_is64 = (zeros >= 48) ? 1 : 0;
    }
}

__device__ __forceinline__ void load_edge(const void* ei, int e, int E, int& s, int& d) {
    if (g_is64) {
        const long long* p = (const long long*)ei;
        s = (int)p[e]; d = (int)p[E + e];
    } else {
        const int* p = (const int*)ei;
        s = p[e]; d = p[E + e];
    }
}

__global__ void k_count(const void* __restrict__ ei, int E) {
    int e = blockIdx.x * blockDim.x + threadIdx.x;
    if (e < E) {
        int s, d; load_edge(ei, e, E, s, d);
        if ((unsigned)d < NN) atomicAdd(&g_cnt[d], 1);
    }
}

// ---------------- scan phase 1: per-block sums ----------------
__global__ void k_bsum() {
    int i = blockIdx.x * 256 + threadIdx.x;
    int c = (i < NN) ? g_cnt[i] : 0;
    #pragma unroll
    for (int o = 16; o; o >>= 1) c += __shfl_down_sync(0xffffffffu, c, o);
    __shared__ int ws[8];
    if ((threadIdx.x & 31) == 0) ws[threadIdx.x >> 5] = c;
    __syncthreads();
    if (threadIdx.x < 8) {
        int v = ws[threadIdx.x];
        #pragma unroll
        for (int o = 4; o; o >>= 1) v += __shfl_down_sync(0xffu, v, o);
        if (threadIdx.x == 0) g_bsum[blockIdx.x] = v;
    }
}

// ---------------- scan phase 2: offsets (block prefix inline) ----------------
__global__ void k_offsets() {
    const int b = blockIdx.x;
    const int t = threadIdx.x;
    __shared__ int sred[8];
    __shared__ int ws[8];
    __shared__ int s_boff;

    int vtot = (t < NB && t <= b) ? g_bsum[t] : 0;
    #pragma unroll
    for (int o = 16; o; o >>= 1) vtot += __shfl_down_sync(0xffffffffu, vtot, o);
    if ((t & 31) == 0) sred[t >> 5] = vtot;
    __syncthreads();
    if (t == 0) {
        int r = 0;
        #pragma unroll
        for (int j = 0; j < 8; j++) r += sred[j];
        s_boff = r - g_bsum[b];
        if (b == NB - 1) g_off[NN] = r;
    }

    int i    = b * 256 + t;
    int c    = (i < NN) ? g_cnt[i] : 0;
    int lane = t & 31, w = t >> 5;
    int inc  = c;
    #pragma unroll
    for (int o = 1; o < 32; o <<= 1) {
        int u = __shfl_up_sync(0xffffffffu, inc, o);
        if (lane >= o) inc += u;
    }
    __syncthreads();
    if (lane == 31) ws[w] = inc;
    __syncthreads();
    if (t == 0) {
        int r = 0;
        #pragma unroll
        for (int j = 0; j < 8; j++) { int q = ws[j]; ws[j] = r; r += q; }
    }
    __syncthreads();
    int excl = s_boff + ws[w] + (inc - c);
    if (i < NN) {
        g_off[i]  = excl;
        g_fill[i] = excl;
        g_dinv[i] = rsqrtf((float)c + 1.0f);
    }
}

__global__ void k_fill(const void* __restrict__ ei, int E) {
    int e = blockIdx.x * blockDim.x + threadIdx.x;
    if (e < E) {
        int s, d; load_edge(ei, e, E, s, d);
        if ((unsigned)s < NN && (unsigned)d < NN) {
            int pos = atomicAdd(&g_fill[d], 1);
            if (pos < EMAX) g_csr_src[pos] = s;
        }
    }
}

// ---------------- tensor-core GEMM (fp16 in, fp32 accum) -> fp16 out ----------------
// PRESCALE: multiply rows by g_dinv before storing (layer 2 only).
template<int N, int LAYER, bool PRESCALE>
__global__ void k_gemm_h(const float* __restrict__ Xin, const float* __restrict__ W) {
    constexpr int K    = 128;
    constexpr int KW   = K / 2;
    constexpr int ROWS = 64;
    constexpr int XSW  = 68;
    constexpr int WSW  = 68;
    constexpr int NW   = N / 2;
    constexpr int NT   = NW / 8;
    extern __shared__ uint32_t smem[];
    uint32_t* sX = smem;                  // ROWS x XSW
    uint32_t* sW = smem + ROWS * XSW;     // N x WSW

    const float* X  = (LAYER == 1) ? Xin : g_h1r;
    uint32_t*    hs = (LAYER == 1) ? (uint32_t*)g_hs1h : (uint32_t*)g_hs2h;

    const int tid  = threadIdx.x;
    const int row0 = blockIdx.x * ROWS;

    const float4* xg = (const float4*)(X + (size_t)row0 * K);
    #pragma unroll
    for (int j = tid; j < ROWS * K / 4; j += 256) {
        float4 v = xg[j];
        int r = j >> 5, wq = (j & 31) << 1;
        __half2 h0 = __floats2half2_rn(v.x, v.y);
        __half2 h1 = __floats2half2_rn(v.z, v.w);
        sX[r * XSW + wq]     = *(uint32_t*)&h0;
        sX[r * XSW + wq + 1] = *(uint32_t*)&h1;
    }
    #pragma unroll
    for (int j = tid; j < N * KW; j += 256) {
        int n = j % N, kp = j / N;
        __half2 h = __floats2half2_rn(W[(2 * kp) * N + n], W[(2 * kp + 1) * N + n]);
        sW[n * WSW + kp] = *(uint32_t*)&h;
    }
    __syncthreads();

    const int warp = tid >> 5, lane = tid & 31;
    const int wr   = (warp & 3) * 16;
    const int wn   = (warp >> 2) * NW;
    const int grp  = lane >> 2, tig = lane & 3;

    float4 acc[NT];
    #pragma unroll
    for (int t = 0; t < NT; t++) acc[t] = make_float4(0.f, 0.f, 0.f, 0.f);

    #pragma unroll
    for (int kb = 0; kb < K / 16; kb++) {
        const uint32_t* ax = sX + (wr + grp) * XSW + kb * 8 + tig;
        uint32_t a0 = ax[0];
        uint32_t a1 = ax[8 * XSW];
        uint32_t a2 = ax[4];
        uint32_t a3 = ax[8 * XSW + 4];
        const uint32_t* bx = sW + (wn + grp) * WSW + kb * 8 + tig;
        #pragma unroll
        for (int t = 0; t < NT; t++) {
            uint32_t b0 = bx[t * 8 * WSW];
            uint32_t b1 = bx[t * 8 * WSW + 4];
            mma_f16(acc[t], a0, a1, a2, a3, b0, b1);
        }
    }

    const int r0 = row0 + wr + grp;
    const int r1 = r0 + 8;
    const float d0 = PRESCALE ? g_dinv[r0] : 1.0f;
    const float d1 = PRESCALE ? g_dinv[r1] : 1.0f;
    #pragma unroll
    for (int t = 0; t < NT; t++) {
        int c = wn + t * 8 + 2 * tig;
        __half2 h0 = __floats2half2_rn(acc[t].x * d0, acc[t].y * d0);
        __half2 h1 = __floats2half2_rn(acc[t].z * d1, acc[t].w * d1);
        hs[((size_t)r0 * N + c) >> 1] = *(uint32_t*)&h0;
        hs[((size_t)r1 * N + c) >> 1] = *(uint32_t*)&h1;
    }
}

// ---------------- pull aggregation ----------------
__device__ __forceinline__ void hacc4s(float4& a, uint2 u, float d) {
    float2 lo = __half22float2(*(__half2*)&u.x);
    float2 hi = __half22float2(*(__half2*)&u.y);
    a.x = fmaf(d, lo.x, a.x); a.y = fmaf(d, lo.y, a.y);
    a.z = fmaf(d, hi.x, a.z); a.w = fmaf(d, hi.y, a.w);
}
__device__ __forceinline__ void hacc2(float2& a, uint32_t u) {
    float2 v = __half22float2(*(__half2*)&u);
    a.x += v.x; a.y += v.y;
}

// layer 1: h unscaled; apply dinv[s] per neighbor, dinv[i] for self and output.
__global__ void k_aggr1(const float* __restrict__ b1) {
    int node = blockIdx.x * 8 + (threadIdx.x >> 5);
    if (node >= NN) return;
    int lane = threadIdx.x & 31;
    const uint2* hs = (const uint2*)g_hs1h;

    float dn = g_dinv[node];
    float4 a0, a1, a2, a3;
    a0 = a1 = a2 = a3 = make_float4(0.f, 0.f, 0.f, 0.f);
    hacc4s(a0, hs[node * 32 + lane], dn);      // self term: dinv[i]*h[i]

    int off0 = g_off[node], off1 = g_off[node + 1];
    for (int base = off0; base < off1; base += 32) {
        int idx = base + lane;
        int   s  = (idx < off1) ? __ldg(&g_csr_src[idx]) : 0;
        float dv = (idx < off1) ? __ldg(&g_dinv[s]) : 0.f;
        int m = min(32, off1 - base);
        int k = 0;
        for (; k + 4 <= m; k += 4) {
            int   s0 = __shfl_sync(0xffffffffu, s, k);
            float d0 = __shfl_sync(0xffffffffu, dv, k);
            int   s1 = __shfl_sync(0xffffffffu, s, k + 1);
            float d1 = __shfl_sync(0xffffffffu, dv, k + 1);
            int   s2 = __shfl_sync(0xffffffffu, s, k + 2);
            float d2 = __shfl_sync(0xffffffffu, dv, k + 2);
            int   s3 = __shfl_sync(0xffffffffu, s, k + 3);
            float d3 = __shfl_sync(0xffffffffu, dv, k + 3);
            uint2 v0 = hs[s0 * 32 + lane];
            uint2 v1 = hs[s1 * 32 + lane];
            uint2 v2 = hs[s2 * 32 + lane];
            uint2 v3 = hs[s3 * 32 + lane];
            hacc4s(a0, v0, d0); hacc4s(a1, v1, d1);
            hacc4s(a2, v2, d2); hacc4s(a3, v3, d3);
        }
        for (; k < m; k++) {
            int   sk = __shfl_sync(0xffffffffu, s, k);
            float dk = __shfl_sync(0xffffffffu, dv, k);
            hacc4s(a0, hs[sk * 32 + lane], dk);
        }
    }
    float4 bb = ((const float4*)b1)[lane];
    float4 r;
    r.x = fmaxf(0.0f, (a0.x + a1.x + a2.x + a3.x) * dn + bb.x);
    r.y = fmaxf(0.0f, (a0.y + a1.y + a2.y + a3.y) * dn + bb.y);
    r.z = fmaxf(0.0f, (a0.z + a1.z + a2.z + a3.z) * dn + bb.z);
    r.w = fmaxf(0.0f, (a0.w + a1.w + a2.w + a3.w) * dn + bb.w);
    ((float4*)g_h1r)[node * 32 + lane] = r;
}

// layer 2: hs2 already dinv-prescaled.
__global__ void k_aggr2(const float* __restrict__ b2, float* __restrict__ out) {
    int node = blockIdx.x * 8 + (threadIdx.x >> 5);
    if (node >= NN) return;
    int lane = threadIdx.x & 31;
    const uint32_t* hs = (const uint32_t*)g_hs2h;

    float2 a0, a1, a2, a3;
    a0 = make_float2(0.f, 0.f);
    hacc2(a0, hs[node * 32 + lane]);                // self term
    a1 = a2 = a3 = make_float2(0.f, 0.f);

    int off0 = g_off[node], off1 = g_off[node + 1];
    for (int base = off0; base < off1; base += 32) {
        int idx = base + lane;
        int s   = (idx < off1) ? __ldg(&g_csr_src[idx]) : 0;
        int m   = min(32, off1 - base);
        int k   = 0;
        for (; k + 4 <= m; k += 4) {
            int s0 = __shfl_sync(0xffffffffu, s, k);
            int s1 = __shfl_sync(0xffffffffu, s, k + 1);
            int s2 = __shfl_sync(0xffffffffu, s, k + 2);
            int s3 = __shfl_sync(0xffffffffu, s, k + 3);
            uint32_t v0 = hs[s0 * 32 + lane];
            uint32_t v1 = hs[s1 * 32 + lane];
            uint32_t v2 = hs[s2 * 32 + lane];
            uint32_t v3 = hs[s3 * 32 + lane];
            hacc2(a0, v0); hacc2(a1, v1); hacc2(a2, v2); hacc2(a3, v3);
        }
        for (; k < m; k++) {
            int sk = __shfl_sync(0xffffffffu, s, k);
            hacc2(a0, hs[sk * 32 + lane]);
        }
    }
    float d   = g_dinv[node];
    float2 bb = ((const float2*)b2)[lane];
    float2 r;
    r.x = (a0.x + a1.x + a2.x + a3.x) * d + bb.x;
    r.y = (a0.y + a1.y + a2.y + a3.y) * d + bb.y;
    ((float2*)out)[node * 32 + lane] = r;
}

// ---------------- launch (fork-join: GEMM1 overlaps CSR build) ----------------
extern "C" void kernel_launch(void* const* d_in, const int* in_sizes, int n_in,
                              void* d_out, int out_size) {
    const float* x  = (const float*)d_in[0];
    const void*  ei = d_in[1];
    const float* W1 = (const float*)d_in[2];
    const float* b1 = (const float*)d_in[3];
    const float* W2 = (const float*)d_in[4];
    const float* b2 = (const float*)d_in[5];
    const int E = in_sizes[1] / 2;

    constexpr int SM1 = (64 * 68 + DH   * 68) * 4;   // 52224 B
    constexpr int SM2 = (64 * 68 + DOUT * 68) * 4;   // 34816 B
    cudaFuncSetAttribute(k_gemm_h<DH, 1, false>,
                         cudaFuncAttributeMaxDynamicSharedMemorySize, SM1);
    cudaFuncSetAttribute(k_gemm_h<DOUT, 2, true>,
                         cudaFuncAttributeMaxDynamicSharedMemorySize, SM2);

    cudaStream_t s2;
    cudaEvent_t evF, evG;
    cudaStreamCreateWithFlags(&s2, cudaStreamNonBlocking);
    cudaEventCreateWithFlags(&evF, cudaEventDisableTiming);
    cudaEventCreateWithFlags(&evG, cudaEventDisableTiming);

    // fork: GEMM1 (independent of CSR) on side stream
    cudaEventRecord(evF, 0);
    cudaStreamWaitEvent(s2, evF, 0);
    k_gemm_h<DH, 1, false><<<NN / 64, 256, SM1, s2>>>(x, W1);
    cudaEventRecord(evG, s2);

    // CSR build on main stream
    k_init   <<<NB, 256>>>((const int*)ei);
    k_count  <<<(E + 255) / 256, 256>>>(ei, E);
    k_bsum   <<<NB, 256>>>();
    k_offsets<<<NB, 256>>>();
    k_fill   <<<(E + 255) / 256, 256>>>(ei, E);

    // join
    cudaStreamWaitEvent(0, evG, 0);

    k_aggr1<<<(NN + 7) / 8, 256>>>(b1);
    k_gemm_h<DOUT, 2, true><<<NN / 64, 256, SM2>>>(nullptr, W2);
    k_aggr2<<<(NN + 7) / 8, 256>>>(b2, (float*)d_out);

    cudaEventDestroy(evF);
    cudaEventDestroy(evG);
    cudaStreamDestroy(s2);
}

// round 11
// speedup vs baseline: 1.0592x; 1.0592x over previous
#include <cuda_runtime.h>
#include <cuda_fp16.h>
#include <cstdint>

#define NN    40000
#define DH    128
#define DOUT  64
#define EMAX  700000
#define NB    157           // ceil(40000/256)

// ---------------- scratch (device globals; no allocation allowed) ----------------
__device__ __align__(16) float  g_dinv[NN];
__device__ __align__(16) __half g_hs1h[NN * DH];   // fp16 dinv-prescaled h1
__device__ __align__(16) __half g_h1rh[NN * DH];   // fp16 relu(layer1 out)
__device__ __align__(16) __half g_hs2h[NN * DOUT]; // fp16 dinv-prescaled h2
__device__ int g_cnt [NN];
__device__ int g_off [NN + 1];
__device__ int g_fill[NN];
__device__ int g_csr_src[EMAX];
__device__ int g_bsum[NB];
__device__ int g_is64;

__device__ __forceinline__ void mma_f16(float4& c, uint32_t a0, uint32_t a1,
                                        uint32_t a2, uint32_t a3,
                                        uint32_t b0, uint32_t b1) {
    asm volatile("mma.sync.aligned.m16n8k16.row.col.f32.f16.f16.f32 "
                 "{%0,%1,%2,%3}, {%4,%5,%6,%7}, {%8,%9}, {%0,%1,%2,%3};"
                 : "+f"(c.x), "+f"(c.y), "+f"(c.z), "+f"(c.w)
                 : "r"(a0), "r"(a1), "r"(a2), "r"(a3), "r"(b0), "r"(b1));
}

// ---------------- init: zero counts, detect edge width ----------------
__global__ void k_init(const int* __restrict__ ei32) {
    int i = blockIdx.x * blockDim.x + threadIdx.x;
    if (i < NN) g_cnt[i] = 0;
    if (i == 0) {
        int zeros = 0;
        #pragma unroll
        for (int j = 1; j < 128; j += 2) zeros += (ei32[j] == 0);
        g_is64 = (zeros >= 48) ? 1 : 0;
    }
}

__device__ __forceinline__ void load_edge(const void* ei, int e, int E, int& s, int& d) {
    if (g_is64) {
        const long long* p = (const long long*)ei;
        s = (int)p[e]; d = (int)p[E + e];
    } else {
        const int* p = (const int*)ei;
        s = p[e]; d = p[E + e];
    }
}

__global__ void k_count(const void* __restrict__ ei, int E) {
    int e = blockIdx.x * blockDim.x + threadIdx.x;
    if (e < E) {
        int s, d; load_edge(ei, e, E, s, d);
        if ((unsigned)d < NN) atomicAdd(&g_cnt[d], 1);
    }
}

// ---------------- scan phase 1: per-block sums ----------------
__global__ void k_bsum() {
    int i = blockIdx.x * 256 + threadIdx.x;
    int c = (i < NN) ? g_cnt[i] : 0;
    #pragma unroll
    for (int o = 16; o; o >>= 1) c += __shfl_down_sync(0xffffffffu, c, o);
    __shared__ int ws[8];
    if ((threadIdx.x & 31) == 0) ws[threadIdx.x >> 5] = c;
    __syncthreads();
    if (threadIdx.x < 8) {
        int v = ws[threadIdx.x];
        #pragma unroll
        for (int o = 4; o; o >>= 1) v += __shfl_down_sync(0xffu, v, o);
        if (threadIdx.x == 0) g_bsum[blockIdx.x] = v;
    }
}

// ---------------- scan phase 2: offsets (block prefix inline) ----------------
__global__ void k_offsets() {
    const int b = blockIdx.x;
    const int t = threadIdx.x;
    __shared__ int sred[8];
    __shared__ int ws[8];
    __shared__ int s_boff;

    int vtot = (t < NB && t <= b) ? g_bsum[t] : 0;
    #pragma unroll
    for (int o = 16; o; o >>= 1) vtot += __shfl_down_sync(0xffffffffu, vtot, o);
    if ((t & 31) == 0) sred[t >> 5] = vtot;
    __syncthreads();
    if (t == 0) {
        int r = 0;
        #pragma unroll
        for (int j = 0; j < 8; j++) r += sred[j];
        s_boff = r - g_bsum[b];
        if (b == NB - 1) g_off[NN] = r;
    }

    int i    = b * 256 + t;
    int c    = (i < NN) ? g_cnt[i] : 0;
    int lane = t & 31, w = t >> 5;
    int inc  = c;
    #pragma unroll
    for (int o = 1; o < 32; o <<= 1) {
        int u = __shfl_up_sync(0xffffffffu, inc, o);
        if (lane >= o) inc += u;
    }
    __syncthreads();
    if (lane == 31) ws[w] = inc;
    __syncthreads();
    if (t == 0) {
        int r = 0;
        #pragma unroll
        for (int j = 0; j < 8; j++) { int q = ws[j]; ws[j] = r; r += q; }
    }
    __syncthreads();
    int excl = s_boff + ws[w] + (inc - c);
    if (i < NN) {
        g_off[i]  = excl;
        g_fill[i] = excl;
        g_dinv[i] = rsqrtf((float)c + 1.0f);
    }
}

__global__ void k_fill(const void* __restrict__ ei, int E) {
    int e = blockIdx.x * blockDim.x + threadIdx.x;
    if (e < E) {
        int s, d; load_edge(ei, e, E, s, d);
        if ((unsigned)s < NN && (unsigned)d < NN) {
            int pos = atomicAdd(&g_fill[d], 1);
            if (pos < EMAX) g_csr_src[pos] = s;
        }
    }
}

// ---------------- tensor-core GEMM (fp16 in, fp32 accum) + dinv prescale -> fp16 ----------------
// LAYER 1: X fp32 (cvt on stage). LAYER 2: X fp16 (plain copy on stage).
template<int N, int LAYER>
__global__ void k_gemm_h(const float* __restrict__ Xin, const float* __restrict__ W) {
    constexpr int K    = 128;
    constexpr int KW   = K / 2;
    constexpr int ROWS = 64;
    constexpr int XSW  = 68;
    constexpr int WSW  = 68;
    constexpr int NW   = N / 2;
    constexpr int NT   = NW / 8;
    extern __shared__ uint32_t smem[];
    uint32_t* sX = smem;                  // ROWS x XSW
    uint32_t* sW = smem + ROWS * XSW;     // N x WSW

    uint32_t* hs = (LAYER == 1) ? (uint32_t*)g_hs1h : (uint32_t*)g_hs2h;

    const int tid  = threadIdx.x;
    const int row0 = blockIdx.x * ROWS;

    if (LAYER == 1) {
        const float4* xg = (const float4*)(Xin + (size_t)row0 * K);
        #pragma unroll
        for (int j = tid; j < ROWS * K / 4; j += 256) {
            float4 v = xg[j];
            int r = j >> 5, wq = (j & 31) << 1;
            __half2 h0 = __floats2half2_rn(v.x, v.y);
            __half2 h1 = __floats2half2_rn(v.z, v.w);
            sX[r * XSW + wq]     = *(uint32_t*)&h0;
            sX[r * XSW + wq + 1] = *(uint32_t*)&h1;
        }
    } else {
        const uint2* xg = (const uint2*)(g_h1rh + (size_t)row0 * K);
        #pragma unroll
        for (int j = tid; j < ROWS * K / 4; j += 256) {
            uint2 v = xg[j];
            int r = j >> 5, wq = (j & 31) << 1;
            sX[r * XSW + wq]     = v.x;
            sX[r * XSW + wq + 1] = v.y;
        }
    }
    #pragma unroll
    for (int j = tid; j < N * KW; j += 256) {
        int n = j % N, kp = j / N;
        __half2 h = __floats2half2_rn(W[(2 * kp) * N + n], W[(2 * kp + 1) * N + n]);
        sW[n * WSW + kp] = *(uint32_t*)&h;
    }
    __syncthreads();

    const int warp = tid >> 5, lane = tid & 31;
    const int wr   = (warp & 3) * 16;
    const int wn   = (warp >> 2) * NW;
    const int grp  = lane >> 2, tig = lane & 3;

    float4 acc[NT];
    #pragma unroll
    for (int t = 0; t < NT; t++) acc[t] = make_float4(0.f, 0.f, 0.f, 0.f);

    #pragma unroll
    for (int kb = 0; kb < K / 16; kb++) {
        const uint32_t* ax = sX + (wr + grp) * XSW + kb * 8 + tig;
        uint32_t a0 = ax[0];
        uint32_t a1 = ax[8 * XSW];
        uint32_t a2 = ax[4];
        uint32_t a3 = ax[8 * XSW + 4];
        const uint32_t* bx = sW + (wn + grp) * WSW + kb * 8 + tig;
        #pragma unroll
        for (int t = 0; t < NT; t++) {
            uint32_t b0 = bx[t * 8 * WSW];
            uint32_t b1 = bx[t * 8 * WSW + 4];
            mma_f16(acc[t], a0, a1, a2, a3, b0, b1);
        }
    }

    const int r0 = row0 + wr + grp;
    const int r1 = r0 + 8;
    const float d0 = g_dinv[r0], d1 = g_dinv[r1];
    #pragma unroll
    for (int t = 0; t < NT; t++) {
        int c = wn + t * 8 + 2 * tig;
        __half2 h0 = __floats2half2_rn(acc[t].x * d0, acc[t].y * d0);
        __half2 h1 = __floats2half2_rn(acc[t].z * d1, acc[t].w * d1);
        hs[((size_t)r0 * N + c) >> 1] = *(uint32_t*)&h0;
        hs[((size_t)r1 * N + c) >> 1] = *(uint32_t*)&h1;
    }
}

// ---------------- pull aggregation (fp16 gather, fp32 accumulate) ----------------
__device__ __forceinline__ void hacc4(float4& a, uint2 u) {
    float2 lo = __half22float2(*(__half2*)&u.x);
    float2 hi = __half22float2(*(__half2*)&u.y);
    a.x += lo.x; a.y += lo.y; a.z += hi.x; a.w += hi.y;
}
__device__ __forceinline__ void hacc2(float2& a, uint32_t u) {
    float2 v = __half22float2(*(__half2*)&u);
    a.x += v.x; a.y += v.y;
}

__global__ void k_aggr1(const float* __restrict__ b1) {
    int node = blockIdx.x * 8 + (threadIdx.x >> 5);
    if (node >= NN) return;
    int lane = threadIdx.x & 31;
    const uint2* hs = (const uint2*)g_hs1h;

    float4 a0, a1, a2, a3;
    a0 = make_float4(0.f, 0.f, 0.f, 0.f);
    hacc4(a0, hs[node * 32 + lane]);          // self term
    a1 = a2 = a3 = make_float4(0.f, 0.f, 0.f, 0.f);

    int off0 = g_off[node], off1 = g_off[node + 1];
    for (int base = off0; base < off1; base += 32) {
        int idx = base + lane;
        int s   = (idx < off1) ? __ldg(&g_csr_src[idx]) : 0;
        int m   = min(32, off1 - base);
        int k   = 0;
        for (; k + 8 <= m; k += 8) {
            int s0 = __shfl_sync(0xffffffffu, s, k);
            int s1 = __shfl_sync(0xffffffffu, s, k + 1);
            int s2 = __shfl_sync(0xffffffffu, s, k + 2);
            int s3 = __shfl_sync(0xffffffffu, s, k + 3);
            int s4 = __shfl_sync(0xffffffffu, s, k + 4);
            int s5 = __shfl_sync(0xffffffffu, s, k + 5);
            int s6 = __shfl_sync(0xffffffffu, s, k + 6);
            int s7 = __shfl_sync(0xffffffffu, s, k + 7);
            uint2 v0 = hs[s0 * 32 + lane];
            uint2 v1 = hs[s1 * 32 + lane];
            uint2 v2 = hs[s2 * 32 + lane];
            uint2 v3 = hs[s3 * 32 + lane];
            uint2 v4 = hs[s4 * 32 + lane];
            uint2 v5 = hs[s5 * 32 + lane];
            uint2 v6 = hs[s6 * 32 + lane];
            uint2 v7 = hs[s7 * 32 + lane];
            hacc4(a0, v0); hacc4(a1, v1); hacc4(a2, v2); hacc4(a3, v3);
            hacc4(a0, v4); hacc4(a1, v5); hacc4(a2, v6); hacc4(a3, v7);
        }
        for (; k < m; k++) {
            int sk = __shfl_sync(0xffffffffu, s, k);
            hacc4(a0, hs[sk * 32 + lane]);
        }
    }
    float d   = g_dinv[node];
    float4 bb = ((const float4*)b1)[lane];
    float rx = fmaxf(0.0f, (a0.x + a1.x + a2.x + a3.x) * d + bb.x);
    float ry = fmaxf(0.0f, (a0.y + a1.y + a2.y + a3.y) * d + bb.y);
    float rz = fmaxf(0.0f, (a0.z + a1.z + a2.z + a3.z) * d + bb.z);
    float rw = fmaxf(0.0f, (a0.w + a1.w + a2.w + a3.w) * d + bb.w);
    __half2 o0 = __floats2half2_rn(rx, ry);
    __half2 o1 = __floats2half2_rn(rz, rw);
    uint2 ov = make_uint2(*(uint32_t*)&o0, *(uint32_t*)&o1);
    ((uint2*)g_h1rh)[node * 32 + lane] = ov;
}

__global__ void k_aggr2(const float* __restrict__ b2, float* __restrict__ out) {
    int node = blockIdx.x * 8 + (threadIdx.x >> 5);
    if (node >= NN) return;
    int lane = threadIdx.x & 31;
    const uint32_t* hs = (const uint32_t*)g_hs2h;

    float2 a0, a1, a2, a3;
    a0 = make_float2(0.f, 0.f);
    hacc2(a0, hs[node * 32 + lane]);                // self term
    a1 = a2 = a3 = make_float2(0.f, 0.f);

    int off0 = g_off[node], off1 = g_off[node + 1];
    for (int base = off0; base < off1; base += 32) {
        int idx = base + lane;
        int s   = (idx < off1) ? __ldg(&g_csr_src[idx]) : 0;
        int m   = min(32, off1 - base);
        int k   = 0;
        for (; k + 8 <= m; k += 8) {
            int s0 = __shfl_sync(0xffffffffu, s, k);
            int s1 = __shfl_sync(0xffffffffu, s, k + 1);
            int s2 = __shfl_sync(0xffffffffu, s, k + 2);
            int s3 = __shfl_sync(0xffffffffu, s, k + 3);
            int s4 = __shfl_sync(0xffffffffu, s, k + 4);
            int s5 = __shfl_sync(0xffffffffu, s, k + 5);
            int s6 = __shfl_sync(0xffffffffu, s, k + 6);
            int s7 = __shfl_sync(0xffffffffu, s, k + 7);
            uint32_t v0 = hs[s0 * 32 + lane];
            uint32_t v1 = hs[s1 * 32 + lane];
            uint32_t v2 = hs[s2 * 32 + lane];
            uint32_t v3 = hs[s3 * 32 + lane];
            uint32_t v4 = hs[s4 * 32 + lane];
            uint32_t v5 = hs[s5 * 32 + lane];
            uint32_t v6 = hs[s6 * 32 + lane];
            uint32_t v7 = hs[s7 * 32 + lane];
            hacc2(a0, v0); hacc2(a1, v1); hacc2(a2, v2); hacc2(a3, v3);
            hacc2(a0, v4); hacc2(a1, v5); hacc2(a2, v6); hacc2(a3, v7);
        }
        for (; k < m; k++) {
            int sk = __shfl_sync(0xffffffffu, s, k);
            hacc2(a0, hs[sk * 32 + lane]);
        }
    }
    float d   = g_dinv[node];
    float2 bb = ((const float2*)b2)[lane];
    float2 r;
    r.x = (a0.x + a1.x + a2.x + a3.x) * d + bb.x;
    r.y = (a0.y + a1.y + a2.y + a3.y) * d + bb.y;
    ((float2*)out)[node * 32 + lane] = r;
}

// ---------------- launch ----------------
extern "C" void kernel_launch(void* const* d_in, const int* in_sizes, int n_in,
                              void* d_out, int out_size) {
    const float* x  = (const float*)d_in[0];
    const void*  ei = d_in[1];
    const float* W1 = (const float*)d_in[2];
    const float* b1 = (const float*)d_in[3];
    const float* W2 = (const float*)d_in[4];
    const float* b2 = (const float*)d_in[5];
    const int E = in_sizes[1] / 2;

    constexpr int SM1 = (64 * 68 + DH   * 68) * 4;   // 52224 B
    constexpr int SM2 = (64 * 68 + DOUT * 68) * 4;   // 34816 B
    cudaFuncSetAttribute(k_gemm_h<DH, 1>,
                         cudaFuncAttributeMaxDynamicSharedMemorySize, SM1);
    cudaFuncSetAttribute(k_gemm_h<DOUT, 2>,
                         cudaFuncAttributeMaxDynamicSharedMemorySize, SM2);

    k_init   <<<NB, 256>>>((const int*)ei);
    k_count  <<<(E + 255) / 256, 256>>>(ei, E);
    k_bsum   <<<NB, 256>>>();
    k_offsets<<<NB, 256>>>();
    k_fill   <<<(E + 255) / 256, 256>>>(ei, E);

    // Layer 1
    k_gemm_h<DH, 1><<<NN / 64, 256, SM1>>>(x, W1);
    k_aggr1<<<(NN + 7) / 8, 256>>>(b1);

    // Layer 2
    k_gemm_h<DOUT, 2><<<NN / 64, 256, SM2>>>(nullptr, W2);
    k_aggr2<<<(NN + 7) / 8, 256>>>(b2, (float*)d_out);
}

// round 12
// speedup vs baseline: 1.1981x; 1.1311x over previous
#include <cuda_runtime.h>
#include <cuda_fp16.h>
#include <cstdint>

#define NN    40000
#define DH    128
#define DOUT  64
#define CAP   64            // max in-degree capacity (Poisson(16): P(>64) ~ 1e-21)
#define NB    157           // ceil(40000/256)

// ---------------- scratch (device globals; no allocation allowed) ----------------
__device__ __align__(16) __half g_hs1h[NN * DH];   // fp16 dinv-prescaled h1
__device__ __align__(16) __half g_h1rh[NN * DH];   // fp16 relu(layer1 out)
__device__ __align__(16) __half g_hs2h[NN * DOUT]; // fp16 dinv-prescaled h2
__device__ int g_cnt [NN];                          // in-degree (excl self)
__device__ int g_slot[NN * CAP];                    // per-node neighbor slots
__device__ int g_is64;

__device__ __forceinline__ void mma_f16(float4& c, uint32_t a0, uint32_t a1,
                                        uint32_t a2, uint32_t a3,
                                        uint32_t b0, uint32_t b1) {
    asm volatile("mma.sync.aligned.m16n8k16.row.col.f32.f16.f16.f32 "
                 "{%0,%1,%2,%3}, {%4,%5,%6,%7}, {%8,%9}, {%0,%1,%2,%3};"
                 : "+f"(c.x), "+f"(c.y), "+f"(c.z), "+f"(c.w)
                 : "r"(a0), "r"(a1), "r"(a2), "r"(a3), "r"(b0), "r"(b1));
}

// ---------------- init: zero counts, detect edge width ----------------
__global__ void k_init(const int* __restrict__ ei32) {
    int i = blockIdx.x * blockDim.x + threadIdx.x;
    if (i < NN) g_cnt[i] = 0;
    if (i == 0) {
        int zeros = 0;
        #pragma unroll
        for (int j = 1; j < 128; j += 2) zeros += (ei32[j] == 0);
        g_is64 = (zeros >= 48) ? 1 : 0;
    }
}

__device__ __forceinline__ void load_edge(const void* ei, int e, int E, int& s, int& d) {
    if (g_is64) {
        const long long* p = (const long long*)ei;
        s = (int)p[e]; d = (int)p[E + e];
    } else {
        const int* p = (const int*)ei;
        s = p[e]; d = p[E + e];
    }
}

// ---------------- fused count + fill: one pass over edges ----------------
__global__ void k_countfill(const void* __restrict__ ei, int E) {
    int e = blockIdx.x * blockDim.x + threadIdx.x;
    if (e < E) {
        int s, d; load_edge(ei, e, E, s, d);
        if ((unsigned)s < NN && (unsigned)d < NN) {
            int pos = atomicAdd(&g_cnt[d], 1);
            if (pos < CAP) g_slot[d * CAP + pos] = s;
        }
    }
}

// ---------------- tensor-core GEMM (fp16 in, fp32 accum) + dinv prescale -> fp16 ----------------
// LAYER 1: X fp32 (cvt on stage). LAYER 2: X fp16 (plain copy on stage).
// dinv computed inline from g_cnt.
template<int N, int LAYER>
__global__ void k_gemm_h(const float* __restrict__ Xin, const float* __restrict__ W) {
    constexpr int K    = 128;
    constexpr int KW   = K / 2;
    constexpr int ROWS = 64;
    constexpr int XSW  = 68;
    constexpr int WSW  = 68;
    constexpr int NW   = N / 2;
    constexpr int NT   = NW / 8;
    extern __shared__ uint32_t smem[];
    uint32_t* sX = smem;                  // ROWS x XSW
    uint32_t* sW = smem + ROWS * XSW;     // N x WSW

    uint32_t* hs = (LAYER == 1) ? (uint32_t*)g_hs1h : (uint32_t*)g_hs2h;

    const int tid  = threadIdx.x;
    const int row0 = blockIdx.x * ROWS;

    if (LAYER == 1) {
        const float4* xg = (const float4*)(Xin + (size_t)row0 * K);
        #pragma unroll
        for (int j = tid; j < ROWS * K / 4; j += 256) {
            float4 v = xg[j];
            int r = j >> 5, wq = (j & 31) << 1;
            __half2 h0 = __floats2half2_rn(v.x, v.y);
            __half2 h1 = __floats2half2_rn(v.z, v.w);
            sX[r * XSW + wq]     = *(uint32_t*)&h0;
            sX[r * XSW + wq + 1] = *(uint32_t*)&h1;
        }
    } else {
        const uint2* xg = (const uint2*)(g_h1rh + (size_t)row0 * K);
        #pragma unroll
        for (int j = tid; j < ROWS * K / 4; j += 256) {
            uint2 v = xg[j];
            int r = j >> 5, wq = (j & 31) << 1;
            sX[r * XSW + wq]     = v.x;
            sX[r * XSW + wq + 1] = v.y;
        }
    }
    #pragma unroll
    for (int j = tid; j < N * KW; j += 256) {
        int n = j % N, kp = j / N;
        __half2 h = __floats2half2_rn(W[(2 * kp) * N + n], W[(2 * kp + 1) * N + n]);
        sW[n * WSW + kp] = *(uint32_t*)&h;
    }
    __syncthreads();

    const int warp = tid >> 5, lane = tid & 31;
    const int wr   = (warp & 3) * 16;
    const int wn   = (warp >> 2) * NW;
    const int grp  = lane >> 2, tig = lane & 3;

    float4 acc[NT];
    #pragma unroll
    for (int t = 0; t < NT; t++) acc[t] = make_float4(0.f, 0.f, 0.f, 0.f);

    #pragma unroll
    for (int kb = 0; kb < K / 16; kb++) {
        const uint32_t* ax = sX + (wr + grp) * XSW + kb * 8 + tig;
        uint32_t a0 = ax[0];
        uint32_t a1 = ax[8 * XSW];
        uint32_t a2 = ax[4];
        uint32_t a3 = ax[8 * XSW + 4];
        const uint32_t* bx = sW + (wn + grp) * WSW + kb * 8 + tig;
        #pragma unroll
        for (int t = 0; t < NT; t++) {
            uint32_t b0 = bx[t * 8 * WSW];
            uint32_t b1 = bx[t * 8 * WSW + 4];
            mma_f16(acc[t], a0, a1, a2, a3, b0, b1);
        }
    }

    const int r0 = row0 + wr + grp;
    const int r1 = r0 + 8;
    const float d0 = rsqrtf((float)g_cnt[r0] + 1.0f);
    const float d1 = rsqrtf((float)g_cnt[r1] + 1.0f);
    #pragma unroll
    for (int t = 0; t < NT; t++) {
        int c = wn + t * 8 + 2 * tig;
        __half2 h0 = __floats2half2_rn(acc[t].x * d0, acc[t].y * d0);
        __half2 h1 = __floats2half2_rn(acc[t].z * d1, acc[t].w * d1);
        hs[((size_t)r0 * N + c) >> 1] = *(uint32_t*)&h0;
        hs[((size_t)r1 * N + c) >> 1] = *(uint32_t*)&h1;
    }
}

// ---------------- pull aggregation (fp16 gather, fp32 accumulate) ----------------
__device__ __forceinline__ void hacc4(float4& a, uint2 u) {
    float2 lo = __half22float2(*(__half2*)&u.x);
    float2 hi = __half22float2(*(__half2*)&u.y);
    a.x += lo.x; a.y += lo.y; a.z += hi.x; a.w += hi.y;
}
__device__ __forceinline__ void hacc2(float2& a, uint32_t u) {
    float2 v = __half22float2(*(__half2*)&u);
    a.x += v.x; a.y += v.y;
}

__global__ void k_aggr1(const float* __restrict__ b1) {
    int node = blockIdx.x * 8 + (threadIdx.x >> 5);
    if (node >= NN) return;
    int lane = threadIdx.x & 31;
    const uint2* hs = (const uint2*)g_hs1h;

    int cnt = g_cnt[node];
    float dn = rsqrtf((float)cnt + 1.0f);
    int m_total = min(cnt, CAP);

    float4 a0, a1, a2, a3;
    a0 = make_float4(0.f, 0.f, 0.f, 0.f);
    hacc4(a0, hs[node * 32 + lane]);          // self term
    a1 = a2 = a3 = make_float4(0.f, 0.f, 0.f, 0.f);

    const int* slots = g_slot + node * CAP;
    for (int base = 0; base < m_total; base += 32) {
        int idx = base + lane;
        int s   = (idx < m_total) ? __ldg(&slots[idx]) : 0;
        int m   = min(32, m_total - base);
        int k   = 0;
        for (; k + 8 <= m; k += 8) {
            int s0 = __shfl_sync(0xffffffffu, s, k);
            int s1 = __shfl_sync(0xffffffffu, s, k + 1);
            int s2 = __shfl_sync(0xffffffffu, s, k + 2);
            int s3 = __shfl_sync(0xffffffffu, s, k + 3);
            int s4 = __shfl_sync(0xffffffffu, s, k + 4);
            int s5 = __shfl_sync(0xffffffffu, s, k + 5);
            int s6 = __shfl_sync(0xffffffffu, s, k + 6);
            int s7 = __shfl_sync(0xffffffffu, s, k + 7);
            uint2 v0 = hs[s0 * 32 + lane];
            uint2 v1 = hs[s1 * 32 + lane];
            uint2 v2 = hs[s2 * 32 + lane];
            uint2 v3 = hs[s3 * 32 + lane];
            uint2 v4 = hs[s4 * 32 + lane];
            uint2 v5 = hs[s5 * 32 + lane];
            uint2 v6 = hs[s6 * 32 + lane];
            uint2 v7 = hs[s7 * 32 + lane];
            hacc4(a0, v0); hacc4(a1, v1); hacc4(a2, v2); hacc4(a3, v3);
            hacc4(a0, v4); hacc4(a1, v5); hacc4(a2, v6); hacc4(a3, v7);
        }
        for (; k < m; k++) {
            int sk = __shfl_sync(0xffffffffu, s, k);
            hacc4(a0, hs[sk * 32 + lane]);
        }
    }
    float4 bb = ((const float4*)b1)[lane];
    float rx = fmaxf(0.0f, (a0.x + a1.x + a2.x + a3.x) * dn + bb.x);
    float ry = fmaxf(0.0f, (a0.y + a1.y + a2.y + a3.y) * dn + bb.y);
    float rz = fmaxf(0.0f, (a0.z + a1.z + a2.z + a3.z) * dn + bb.z);
    float rw = fmaxf(0.0f, (a0.w + a1.w + a2.w + a3.w) * dn + bb.w);
    __half2 o0 = __floats2half2_rn(rx, ry);
    __half2 o1 = __floats2half2_rn(rz, rw);
    uint2 ov = make_uint2(*(uint32_t*)&o0, *(uint32_t*)&o1);
    ((uint2*)g_h1rh)[node * 32 + lane] = ov;
}

__global__ void k_aggr2(const float* __restrict__ b2, float* __restrict__ out) {
    int node = blockIdx.x * 8 + (threadIdx.x >> 5);
    if (node >= NN) return;
    int lane = threadIdx.x & 31;
    const uint32_t* hs = (const uint32_t*)g_hs2h;

    int cnt = g_cnt[node];
    float dn = rsqrtf((float)cnt + 1.0f);
    int m_total = min(cnt, CAP);

    float2 a0, a1, a2, a3;
    a0 = make_float2(0.f, 0.f);
    hacc2(a0, hs[node * 32 + lane]);                // self term
    a1 = a2 = a3 = make_float2(0.f, 0.f);

    const int* slots = g_slot + node * CAP;
    for (int base = 0; base < m_total; base += 32) {
        int idx = base + lane;
        int s   = (idx < m_total) ? __ldg(&slots[idx]) : 0;
        int m   = min(32, m_total - base);
        int k   = 0;
        for (; k + 8 <= m; k += 8) {
            int s0 = __shfl_sync(0xffffffffu, s, k);
            int s1 = __shfl_sync(0xffffffffu, s, k + 1);
            int s2 = __shfl_sync(0xffffffffu, s, k + 2);
            int s3 = __shfl_sync(0xffffffffu, s, k + 3);
            int s4 = __shfl_sync(0xffffffffu, s, k + 4);
            int s5 = __shfl_sync(0xffffffffu, s, k + 5);
            int s6 = __shfl_sync(0xffffffffu, s, k + 6);
            int s7 = __shfl_sync(0xffffffffu, s, k + 7);
            uint32_t v0 = hs[s0 * 32 + lane];
            uint32_t v1 = hs[s1 * 32 + lane];
            uint32_t v2 = hs[s2 * 32 + lane];
            uint32_t v3 = hs[s3 * 32 + lane];
            uint32_t v4 = hs[s4 * 32 + lane];
            uint32_t v5 = hs[s5 * 32 + lane];
            uint32_t v6 = hs[s6 * 32 + lane];
            uint32_t v7 = hs[s7 * 32 + lane];
            hacc2(a0, v0); hacc2(a1, v1); hacc2(a2, v2); hacc2(a3, v3);
            hacc2(a0, v4); hacc2(a1, v5); hacc2(a2, v6); hacc2(a3, v7);
        }
        for (; k < m; k++) {
            int sk = __shfl_sync(0xffffffffu, s, k);
            hacc2(a0, hs[sk * 32 + lane]);
        }
    }
    float2 bb = ((const float2*)b2)[lane];
    float2 r;
    r.x = (a0.x + a1.x + a2.x + a3.x) * dn + bb.x;
    r.y = (a0.y + a1.y + a2.y + a3.y) * dn + bb.y;
    ((float2*)out)[node * 32 + lane] = r;
}

// ---------------- launch ----------------
extern "C" void kernel_launch(void* const* d_in, const int* in_sizes, int n_in,
                              void* d_out, int out_size) {
    const float* x  = (const float*)d_in[0];
    const void*  ei = d_in[1];
    const float* W1 = (const float*)d_in[2];
    const float* b1 = (const float*)d_in[3];
    const float* W2 = (const float*)d_in[4];
    const float* b2 = (const float*)d_in[5];
    const int E = in_sizes[1] / 2;

    constexpr int SM1 = (64 * 68 + DH   * 68) * 4;   // 52224 B
    constexpr int SM2 = (64 * 68 + DOUT * 68) * 4;   // 34816 B
    cudaFuncSetAttribute(k_gemm_h<DH, 1>,
                         cudaFuncAttributeMaxDynamicSharedMemorySize, SM1);
    cudaFuncSetAttribute(k_gemm_h<DOUT, 2>,
                         cudaFuncAttributeMaxDynamicSharedMemorySize, SM2);

    k_init     <<<NB, 256>>>((const int*)ei);
    k_countfill<<<(E + 255) / 256, 256>>>(ei, E);

    // Layer 1
    k_gemm_h<DH, 1><<<NN / 64, 256, SM1>>>(x, W1);
    k_aggr1<<<(NN + 7) / 8, 256>>>(b1);

    // Layer 2
    k_gemm_h<DOUT, 2><<<NN / 64, 256, SM2>>>(nullptr, W2);
    k_aggr2<<<(NN + 7) / 8, 256>>>(b2, (float*)d_out);
}

// round 13
// speedup vs baseline: 1.2060x; 1.0066x over previous
#include <cuda_runtime.h>
#include <cuda_fp16.h>
#include <cstdint>

#define NN    40000
#define DH    128
#define DOUT  64
#define CAP   64            // max in-degree capacity (Poisson(16): P(>64) ~ 1e-21)
#define NB    157           // ceil(40000/256)

// ---------------- scratch (device globals; no allocation allowed) ----------------
__device__ __align__(16) __half g_hs1h[NN * DH];   // fp16 dinv-prescaled h1
__device__ __align__(16) __half g_h1rh[NN * DH];   // fp16 relu(layer1 out)
__device__ __align__(16) __half g_hs2h[NN * DOUT]; // fp16 dinv-prescaled h2
__device__ int g_cnt [NN];                          // in-degree (excl self)
__device__ int g_slot[NN * CAP];                    // per-node neighbor slots
__device__ int g_is64;

__device__ __forceinline__ void mma_f16(float4& c, uint32_t a0, uint32_t a1,
                                        uint32_t a2, uint32_t a3,
                                        uint32_t b0, uint32_t b1) {
    asm volatile("mma.sync.aligned.m16n8k16.row.col.f32.f16.f16.f32 "
                 "{%0,%1,%2,%3}, {%4,%5,%6,%7}, {%8,%9}, {%0,%1,%2,%3};"
                 : "+f"(c.x), "+f"(c.y), "+f"(c.z), "+f"(c.w)
                 : "r"(a0), "r"(a1), "r"(a2), "r"(a3), "r"(b0), "r"(b1));
}

__device__ __forceinline__ __half2 h2(uint32_t u) { return *(__half2*)&u; }

// ---------------- init: zero counts, detect edge width ----------------
__global__ void k_init(const int* __restrict__ ei32) {
    int i = blockIdx.x * blockDim.x + threadIdx.x;
    if (i < NN) g_cnt[i] = 0;
    if (i == 0) {
        int zeros = 0;
        #pragma unroll
        for (int j = 1; j < 128; j += 2) zeros += (ei32[j] == 0);
        g_is64 = (zeros >= 48) ? 1 : 0;
    }
}

__device__ __forceinline__ void load_edge(const void* ei, int e, int E, int& s, int& d) {
    if (g_is64) {
        const long long* p = (const long long*)ei;
        s = (int)p[e]; d = (int)p[E + e];
    } else {
        const int* p = (const int*)ei;
        s = p[e]; d = p[E + e];
    }
}

// ---------------- fused count + fill: one pass over edges ----------------
__global__ void k_countfill(const void* __restrict__ ei, int E) {
    int e = blockIdx.x * blockDim.x + threadIdx.x;
    if (e < E) {
        int s, d; load_edge(ei, e, E, s, d);
        if ((unsigned)s < NN && (unsigned)d < NN) {
            int pos = atomicAdd(&g_cnt[d], 1);
            if (pos < CAP) g_slot[d * CAP + pos] = s;
        }
    }
}

// ---------------- tensor-core GEMM (fp16 in, fp32 accum) + dinv prescale -> fp16 ----------------
template<int N, int LAYER>
__global__ void k_gemm_h(const float* __restrict__ Xin, const float* __restrict__ W) {
    constexpr int K    = 128;
    constexpr int KW   = K / 2;
    constexpr int ROWS = 64;
    constexpr int XSW  = 68;
    constexpr int WSW  = 68;
    constexpr int NW   = N / 2;
    constexpr int NT   = NW / 8;
    extern __shared__ uint32_t smem[];
    uint32_t* sX = smem;                  // ROWS x XSW
    uint32_t* sW = smem + ROWS * XSW;     // N x WSW

    uint32_t* hs = (LAYER == 1) ? (uint32_t*)g_hs1h : (uint32_t*)g_hs2h;

    const int tid  = threadIdx.x;
    const int row0 = blockIdx.x * ROWS;

    if (LAYER == 1) {
        const float4* xg = (const float4*)(Xin + (size_t)row0 * K);
        #pragma unroll
        for (int j = tid; j < ROWS * K / 4; j += 256) {
            float4 v = xg[j];
            int r = j >> 5, wq = (j & 31) << 1;
            __half2 h0 = __floats2half2_rn(v.x, v.y);
            __half2 h1 = __floats2half2_rn(v.z, v.w);
            sX[r * XSW + wq]     = *(uint32_t*)&h0;
            sX[r * XSW + wq + 1] = *(uint32_t*)&h1;
        }
    } else {
        const uint2* xg = (const uint2*)(g_h1rh + (size_t)row0 * K);
        #pragma unroll
        for (int j = tid; j < ROWS * K / 4; j += 256) {
            uint2 v = xg[j];
            int r = j >> 5, wq = (j & 31) << 1;
            sX[r * XSW + wq]     = v.x;
            sX[r * XSW + wq + 1] = v.y;
        }
    }
    #pragma unroll
    for (int j = tid; j < N * KW; j += 256) {
        int n = j % N, kp = j / N;
        __half2 h = __floats2half2_rn(W[(2 * kp) * N + n], W[(2 * kp + 1) * N + n]);
        sW[n * WSW + kp] = *(uint32_t*)&h;
    }
    __syncthreads();

    const int warp = tid >> 5, lane = tid & 31;
    const int wr   = (warp & 3) * 16;
    const int wn   = (warp >> 2) * NW;
    const int grp  = lane >> 2, tig = lane & 3;

    float4 acc[NT];
    #pragma unroll
    for (int t = 0; t < NT; t++) acc[t] = make_float4(0.f, 0.f, 0.f, 0.f);

    #pragma unroll
    for (int kb = 0; kb < K / 16; kb++) {
        const uint32_t* ax = sX + (wr + grp) * XSW + kb * 8 + tig;
        uint32_t a0 = ax[0];
        uint32_t a1 = ax[8 * XSW];
        uint32_t a2 = ax[4];
        uint32_t a3 = ax[8 * XSW + 4];
        const uint32_t* bx = sW + (wn + grp) * WSW + kb * 8 + tig;
        #pragma unroll
        for (int t = 0; t < NT; t++) {
            uint32_t b0 = bx[t * 8 * WSW];
            uint32_t b1 = bx[t * 8 * WSW + 4];
            mma_f16(acc[t], a0, a1, a2, a3, b0, b1);
        }
    }

    const int r0 = row0 + wr + grp;
    const int r1 = r0 + 8;
    const float d0 = rsqrtf((float)g_cnt[r0] + 1.0f);
    const float d1 = rsqrtf((float)g_cnt[r1] + 1.0f);
    #pragma unroll
    for (int t = 0; t < NT; t++) {
        int c = wn + t * 8 + 2 * tig;
        __half2 h0 = __floats2half2_rn(acc[t].x * d0, acc[t].y * d0);
        __half2 h1 = __floats2half2_rn(acc[t].z * d1, acc[t].w * d1);
        hs[((size_t)r0 * N + c) >> 1] = *(uint32_t*)&h0;
        hs[((size_t)r1 * N + c) >> 1] = *(uint32_t*)&h1;
    }
}

// ---------------- pull aggregation (fp16 gather, fp16 pair-sum, fp32 accumulate) ----------------
__device__ __forceinline__ void hacc4(float4& a, uint2 u) {
    float2 lo = __half22float2(*(__half2*)&u.x);
    float2 hi = __half22float2(*(__half2*)&u.y);
    a.x += lo.x; a.y += lo.y; a.z += hi.x; a.w += hi.y;
}
__device__ __forceinline__ void hacc4p(float4& a, __half2 px, __half2 py) {
    float2 lo = __half22float2(px);
    float2 hi = __half22float2(py);
    a.x += lo.x; a.y += lo.y; a.z += hi.x; a.w += hi.y;
}
__device__ __forceinline__ void hacc2(float2& a, uint32_t u) {
    float2 v = __half22float2(*(__half2*)&u);
    a.x += v.x; a.y += v.y;
}
__device__ __forceinline__ void hacc2p(float2& a, __half2 p) {
    float2 v = __half22float2(p);
    a.x += v.x; a.y += v.y;
}

__global__ void k_aggr1(const float* __restrict__ b1) {
    int node = blockIdx.x * 8 + (threadIdx.x >> 5);
    if (node >= NN) return;
    int lane = threadIdx.x & 31;
    const uint2* hs = (const uint2*)g_hs1h;

    int cnt = g_cnt[node];
    float dn = rsqrtf((float)cnt + 1.0f);
    int m_total = min(cnt, CAP);

    float4 a0, a1, a2, a3;
    a0 = make_float4(0.f, 0.f, 0.f, 0.f);
    hacc4(a0, hs[node * 32 + lane]);          // self term
    a1 = a2 = a3 = make_float4(0.f, 0.f, 0.f, 0.f);

    const int* slots = g_slot + node * CAP;
    for (int base = 0; base < m_total; base += 32) {
        int idx = base + lane;
        int s   = (idx < m_total) ? __ldg(&slots[idx]) : 0;
        int m   = min(32, m_total - base);
        int k   = 0;
        for (; k + 8 <= m; k += 8) {
            int s0 = __shfl_sync(0xffffffffu, s, k);
            int s1 = __shfl_sync(0xffffffffu, s, k + 1);
            int s2 = __shfl_sync(0xffffffffu, s, k + 2);
            int s3 = __shfl_sync(0xffffffffu, s, k + 3);
            int s4 = __shfl_sync(0xffffffffu, s, k + 4);
            int s5 = __shfl_sync(0xffffffffu, s, k + 5);
            int s6 = __shfl_sync(0xffffffffu, s, k + 6);
            int s7 = __shfl_sync(0xffffffffu, s, k + 7);
            uint2 v0 = hs[s0 * 32 + lane];
            uint2 v1 = hs[s1 * 32 + lane];
            uint2 v2 = hs[s2 * 32 + lane];
            uint2 v3 = hs[s3 * 32 + lane];
            uint2 v4 = hs[s4 * 32 + lane];
            uint2 v5 = hs[s5 * 32 + lane];
            uint2 v6 = hs[s6 * 32 + lane];
            uint2 v7 = hs[s7 * 32 + lane];
            // fp16 pair pre-reduction (one HADD2 per word pair)
            __half2 p0x = __hadd2(h2(v0.x), h2(v1.x)), p0y = __hadd2(h2(v0.y), h2(v1.y));
            __half2 p1x = __hadd2(h2(v2.x), h2(v3.x)), p1y = __hadd2(h2(v2.y), h2(v3.y));
            __half2 p2x = __hadd2(h2(v4.x), h2(v5.x)), p2y = __hadd2(h2(v4.y), h2(v5.y));
            __half2 p3x = __hadd2(h2(v6.x), h2(v7.x)), p3y = __hadd2(h2(v6.y), h2(v7.y));
            hacc4p(a0, p0x, p0y); hacc4p(a1, p1x, p1y);
            hacc4p(a2, p2x, p2y); hacc4p(a3, p3x, p3y);
        }
        for (; k < m; k++) {
            int sk = __shfl_sync(0xffffffffu, s, k);
            hacc4(a0, hs[sk * 32 + lane]);
        }
    }
    float4 bb = ((const float4*)b1)[lane];
    float rx = fmaxf(0.0f, (a0.x + a1.x + a2.x + a3.x) * dn + bb.x);
    float ry = fmaxf(0.0f, (a0.y + a1.y + a2.y + a3.y) * dn + bb.y);
    float rz = fmaxf(0.0f, (a0.z + a1.z + a2.z + a3.z) * dn + bb.z);
    float rw = fmaxf(0.0f, (a0.w + a1.w + a2.w + a3.w) * dn + bb.w);
    __half2 o0 = __floats2half2_rn(rx, ry);
    __half2 o1 = __floats2half2_rn(rz, rw);
    uint2 ov = make_uint2(*(uint32_t*)&o0, *(uint32_t*)&o1);
    ((uint2*)g_h1rh)[node * 32 + lane] = ov;
}

__global__ void k_aggr2(const float* __restrict__ b2, float* __restrict__ out) {
    int node = blockIdx.x * 8 + (threadIdx.x >> 5);
    if (node >= NN) return;
    int lane = threadIdx.x & 31;
    const uint32_t* hs = (const uint32_t*)g_hs2h;

    int cnt = g_cnt[node];
    float dn = rsqrtf((float)cnt + 1.0f);
    int m_total = min(cnt, CAP);

    float2 a0, a1, a2, a3;
    a0 = make_float2(0.f, 0.f);
    hacc2(a0, hs[node * 32 + lane]);                // self term
    a1 = a2 = a3 = make_float2(0.f, 0.f);

    const int* slots = g_slot + node * CAP;
    for (int base = 0; base < m_total; base += 32) {
        int idx = base + lane;
        int s   = (idx < m_total) ? __ldg(&slots[idx]) : 0;
        int m   = min(32, m_total - base);
        int k   = 0;
        for (; k + 8 <= m; k += 8) {
            int s0 = __shfl_sync(0xffffffffu, s, k);
            int s1 = __shfl_sync(0xffffffffu, s, k + 1);
            int s2 = __shfl_sync(0xffffffffu, s, k + 2);
            int s3 = __shfl_sync(0xffffffffu, s, k + 3);
            int s4 = __shfl_sync(0xffffffffu, s, k + 4);
            int s5 = __shfl_sync(0xffffffffu, s, k + 5);
            int s6 = __shfl_sync(0xffffffffu, s, k + 6);
            int s7 = __shfl_sync(0xffffffffu, s, k + 7);
            uint32_t v0 = hs[s0 * 32 + lane];
            uint32_t v1 = hs[s1 * 32 + lane];
            uint32_t v2 = hs[s2 * 32 + lane];
            uint32_t v3 = hs[s3 * 32 + lane];
            uint32_t v4 = hs[s4 * 32 + lane];
            uint32_t v5 = hs[s5 * 32 + lane];
            uint32_t v6 = hs[s6 * 32 + lane];
            uint32_t v7 = hs[s7 * 32 + lane];
            __half2 p0 = __hadd2(h2(v0), h2(v1));
            __half2 p1 = __hadd2(h2(v2), h2(v3));
            __half2 p2 = __hadd2(h2(v4), h2(v5));
            __half2 p3 = __hadd2(h2(v6), h2(v7));
            hacc2p(a0, p0); hacc2p(a1, p1); hacc2p(a2, p2); hacc2p(a3, p3);
        }
        for (; k < m; k++) {
            int sk = __shfl_sync(0xffffffffu, s, k);
            hacc2(a0, hs[sk * 32 + lane]);
        }
    }
    float2 bb = ((const float2*)b2)[lane];
    float2 r;
    r.x = (a0.x + a1.x + a2.x + a3.x) * dn + bb.x;
    r.y = (a0.y + a1.y + a2.y + a3.y) * dn + bb.y;
    ((float2*)out)[node * 32 + lane] = r;
}

// ---------------- launch ----------------
extern "C" void kernel_launch(void* const* d_in, const int* in_sizes, int n_in,
                              void* d_out, int out_size) {
    const float* x  = (const float*)d_in[0];
    const void*  ei = d_in[1];
    const float* W1 = (const float*)d_in[2];
    const float* b1 = (const float*)d_in[3];
    const float* W2 = (const float*)d_in[4];
    const float* b2 = (const float*)d_in[5];
    const int E = in_sizes[1] / 2;

    constexpr int SM1 = (64 * 68 + DH   * 68) * 4;   // 52224 B
    constexpr int SM2 = (64 * 68 + DOUT * 68) * 4;   // 34816 B
    cudaFuncSetAttribute(k_gemm_h<DH, 1>,
                         cudaFuncAttributeMaxDynamicSharedMemorySize, SM1);
    cudaFuncSetAttribute(k_gemm_h<DOUT, 2>,
                         cudaFuncAttributeMaxDynamicSharedMemorySize, SM2);

    k_init     <<<NB, 256>>>((const int*)ei);
    k_countfill<<<(E + 255) / 256, 256>>>(ei, E);

    // Layer 1
    k_gemm_h<DH, 1><<<NN / 64, 256, SM1>>>(x, W1);
    k_aggr1<<<(NN + 7) / 8, 256>>>(b1);

    // Layer 2
    k_gemm_h<DOUT, 2><<<NN / 64, 256, SM2>>>(nullptr, W2);
    k_aggr2<<<(NN + 7) / 8, 256>>>(b2, (float*)d_out);
}

// round 14
// speedup vs baseline: 1.2267x; 1.0171x over previous
#include <cuda_runtime.h>
#include <cuda_fp16.h>
#include <cstdint>

#define NN    40000
#define DH    128
#define DOUT  64
#define CAP   64            // max in-degree capacity (Poisson(16): P(>64) ~ 1e-21)
#define NB    157           // ceil(40000/256)

// ---------------- scratch (device globals; no allocation allowed) ----------------
// +1 row: index NN is an all-zero row used to pad gather loops to the unroll width.
__device__ __align__(16) __half g_hs1h[(NN + 1) * DH];
__device__ __align__(16) __half g_h1rh[NN * DH];
__device__ __align__(16) __half g_hs2h[(NN + 1) * DOUT];
__device__ int g_cnt [NN];
__device__ int g_slot[NN * CAP];
__device__ int g_is64;

__device__ __forceinline__ void mma_f16(float4& c, uint32_t a0, uint32_t a1,
                                        uint32_t a2, uint32_t a3,
                                        uint32_t b0, uint32_t b1) {
    asm volatile("mma.sync.aligned.m16n8k16.row.col.f32.f16.f16.f32 "
                 "{%0,%1,%2,%3}, {%4,%5,%6,%7}, {%8,%9}, {%0,%1,%2,%3};"
                 : "+f"(c.x), "+f"(c.y), "+f"(c.z), "+f"(c.w)
                 : "r"(a0), "r"(a1), "r"(a2), "r"(a3), "r"(b0), "r"(b1));
}

__device__ __forceinline__ __half2 h2(uint32_t u) { return *(__half2*)&u; }

// ---------------- init: zero counts + zero pad rows, detect edge width ----------------
__global__ void k_init(const int* __restrict__ ei32) {
    int i = blockIdx.x * blockDim.x + threadIdx.x;
    if (i < NN) g_cnt[i] = 0;
    if (blockIdx.x == 0) {
        int t = threadIdx.x;
        if (t < DH / 2)   ((uint32_t*)g_hs1h)[NN * (DH / 2)   + t] = 0;   // zero row L1
        if (t < DOUT / 2) ((uint32_t*)g_hs2h)[NN * (DOUT / 2) + t] = 0;   // zero row L2
        if (t == 0) {
            int zeros = 0;
            #pragma unroll
            for (int j = 1; j < 128; j += 2) zeros += (ei32[j] == 0);
            g_is64 = (zeros >= 48) ? 1 : 0;
        }
    }
}

__device__ __forceinline__ void load_edge(const void* ei, int e, int E, int& s, int& d) {
    if (g_is64) {
        const long long* p = (const long long*)ei;
        s = (int)p[e]; d = (int)p[E + e];
    } else {
        const int* p = (const int*)ei;
        s = p[e]; d = p[E + e];
    }
}

// ---------------- fused count + fill: one pass over edges ----------------
__global__ void k_countfill(const void* __restrict__ ei, int E) {
    int e = blockIdx.x * blockDim.x + threadIdx.x;
    if (e < E) {
        int s, d; load_edge(ei, e, E, s, d);
        if ((unsigned)s < NN && (unsigned)d < NN) {
            int pos = atomicAdd(&g_cnt[d], 1);
            if (pos < CAP) g_slot[d * CAP + pos] = s;
        }
    }
}

// ---------------- tensor-core GEMM (fp16 in, fp32 accum) + dinv prescale -> fp16 ----------------
template<int N, int LAYER>
__global__ void k_gemm_h(const float* __restrict__ Xin, const float* __restrict__ W) {
    constexpr int K    = 128;
    constexpr int KW   = K / 2;
    constexpr int ROWS = 64;
    constexpr int XSW  = 68;
    constexpr int WSW  = 68;
    constexpr int NW   = N / 2;
    constexpr int NT   = NW / 8;
    extern __shared__ uint32_t smem[];
    uint32_t* sX = smem;                  // ROWS x XSW
    uint32_t* sW = smem + ROWS * XSW;     // N x WSW

    uint32_t* hs = (LAYER == 1) ? (uint32_t*)g_hs1h : (uint32_t*)g_hs2h;

    const int tid  = threadIdx.x;
    const int row0 = blockIdx.x * ROWS;

    if (LAYER == 1) {
        const float4* xg = (const float4*)(Xin + (size_t)row0 * K);
        #pragma unroll
        for (int j = tid; j < ROWS * K / 4; j += 256) {
            float4 v = xg[j];
            int r = j >> 5, wq = (j & 31) << 1;
            __half2 h0 = __floats2half2_rn(v.x, v.y);
            __half2 h1 = __floats2half2_rn(v.z, v.w);
            sX[r * XSW + wq]     = *(uint32_t*)&h0;
            sX[r * XSW + wq + 1] = *(uint32_t*)&h1;
        }
    } else {
        const uint2* xg = (const uint2*)(g_h1rh + (size_t)row0 * K);
        #pragma unroll
        for (int j = tid; j < ROWS * K / 4; j += 256) {
            uint2 v = xg[j];
            int r = j >> 5, wq = (j & 31) << 1;
            sX[r * XSW + wq]     = v.x;
            sX[r * XSW + wq + 1] = v.y;
        }
    }
    #pragma unroll
    for (int j = tid; j < N * KW; j += 256) {
        int n = j % N, kp = j / N;
        __half2 h = __floats2half2_rn(W[(2 * kp) * N + n], W[(2 * kp + 1) * N + n]);
        sW[n * WSW + kp] = *(uint32_t*)&h;
    }
    __syncthreads();

    const int warp = tid >> 5, lane = tid & 31;
    const int wr   = (warp & 3) * 16;
    const int wn   = (warp >> 2) * NW;
    const int grp  = lane >> 2, tig = lane & 3;

    float4 acc[NT];
    #pragma unroll
    for (int t = 0; t < NT; t++) acc[t] = make_float4(0.f, 0.f, 0.f, 0.f);

    #pragma unroll
    for (int kb = 0; kb < K / 16; kb++) {
        const uint32_t* ax = sX + (wr + grp) * XSW + kb * 8 + tig;
        uint32_t a0 = ax[0];
        uint32_t a1 = ax[8 * XSW];
        uint32_t a2 = ax[4];
        uint32_t a3 = ax[8 * XSW + 4];
        const uint32_t* bx = sW + (wn + grp) * WSW + kb * 8 + tig;
        #pragma unroll
        for (int t = 0; t < NT; t++) {
            uint32_t b0 = bx[t * 8 * WSW];
            uint32_t b1 = bx[t * 8 * WSW + 4];
            mma_f16(acc[t], a0, a1, a2, a3, b0, b1);
        }
    }

    const int r0 = row0 + wr + grp;
    const int r1 = r0 + 8;
    const float d0 = rsqrtf((float)g_cnt[r0] + 1.0f);
    const float d1 = rsqrtf((float)g_cnt[r1] + 1.0f);
    #pragma unroll
    for (int t = 0; t < NT; t++) {
        int c = wn + t * 8 + 2 * tig;
        __half2 h0 = __floats2half2_rn(acc[t].x * d0, acc[t].y * d0);
        __half2 h1 = __floats2half2_rn(acc[t].z * d1, acc[t].w * d1);
        hs[((size_t)r0 * N + c) >> 1] = *(uint32_t*)&h0;
        hs[((size_t)r1 * N + c) >> 1] = *(uint32_t*)&h1;
    }
}

// ---------------- pull aggregation (fp16 gather, fp16 pair-sum, fp32 accumulate) ----------------
__device__ __forceinline__ void hacc4(float4& a, uint2 u) {
    float2 lo = __half22float2(*(__half2*)&u.x);
    float2 hi = __half22float2(*(__half2*)&u.y);
    a.x += lo.x; a.y += lo.y; a.z += hi.x; a.w += hi.y;
}
__device__ __forceinline__ void hacc4p(float4& a, __half2 px, __half2 py) {
    float2 lo = __half22float2(px);
    float2 hi = __half22float2(py);
    a.x += lo.x; a.y += lo.y; a.z += hi.x; a.w += hi.y;
}
__device__ __forceinline__ void hacc2(float2& a, uint32_t u) {
    float2 v = __half22float2(*(__half2*)&u);
    a.x += v.x; a.y += v.y;
}
__device__ __forceinline__ void hacc2p(float2& a, __half2 p) {
    float2 v = __half22float2(p);
    a.x += v.x; a.y += v.y;
}

__global__ void __launch_bounds__(256, 6) k_aggr1(const float* __restrict__ b1) {
    int node = blockIdx.x * 8 + (threadIdx.x >> 5);
    if (node >= NN) return;
    int lane = threadIdx.x & 31;
    const uint2* hs = (const uint2*)g_hs1h;

    int cnt = g_cnt[node];
    float dn = rsqrtf((float)cnt + 1.0f);
    int m_total = min(cnt, CAP);
    int padded  = (m_total + 7) & ~7;          // multiple of 8; pad slots -> zero row NN

    float4 a0, a1, a2, a3;
    a0 = make_float4(0.f, 0.f, 0.f, 0.f);
    hacc4(a0, hs[node * 32 + lane]);           // self term
    a1 = a2 = a3 = make_float4(0.f, 0.f, 0.f, 0.f);

    const int* slots = g_slot + node * CAP;
    for (int base = 0; base < padded; base += 32) {
        int idx = base + lane;
        int s   = (idx < m_total) ? __ldg(&slots[idx]) : NN;   // NN = zero row
        int m   = min(32, padded - base);                      // multiple of 8
        for (int k = 0; k < m; k += 8) {
            int s0 = __shfl_sync(0xffffffffu, s, k);
            int s1 = __shfl_sync(0xffffffffu, s, k + 1);
            int s2 = __shfl_sync(0xffffffffu, s, k + 2);
            int s3 = __shfl_sync(0xffffffffu, s, k + 3);
            int s4 = __shfl_sync(0xffffffffu, s, k + 4);
            int s5 = __shfl_sync(0xffffffffu, s, k + 5);
            int s6 = __shfl_sync(0xffffffffu, s, k + 6);
            int s7 = __shfl_sync(0xffffffffu, s, k + 7);
            uint2 v0 = hs[s0 * 32 + lane];
            uint2 v1 = hs[s1 * 32 + lane];
            uint2 v2 = hs[s2 * 32 + lane];
            uint2 v3 = hs[s3 * 32 + lane];
            uint2 v4 = hs[s4 * 32 + lane];
            uint2 v5 = hs[s5 * 32 + lane];
            uint2 v6 = hs[s6 * 32 + lane];
            uint2 v7 = hs[s7 * 32 + lane];
            __half2 p0x = __hadd2(h2(v0.x), h2(v1.x)), p0y = __hadd2(h2(v0.y), h2(v1.y));
            __half2 p1x = __hadd2(h2(v2.x), h2(v3.x)), p1y = __hadd2(h2(v2.y), h2(v3.y));
            __half2 p2x = __hadd2(h2(v4.x), h2(v5.x)), p2y = __hadd2(h2(v4.y), h2(v5.y));
            __half2 p3x = __hadd2(h2(v6.x), h2(v7.x)), p3y = __hadd2(h2(v6.y), h2(v7.y));
            hacc4p(a0, p0x, p0y); hacc4p(a1, p1x, p1y);
            hacc4p(a2, p2x, p2y); hacc4p(a3, p3x, p3y);
        }
    }
    float4 bb = ((const float4*)b1)[lane];
    float rx = fmaxf(0.0f, (a0.x + a1.x + a2.x + a3.x) * dn + bb.x);
    float ry = fmaxf(0.0f, (a0.y + a1.y + a2.y + a3.y) * dn + bb.y);
    float rz = fmaxf(0.0f, (a0.z + a1.z + a2.z + a3.z) * dn + bb.z);
    float rw = fmaxf(0.0f, (a0.w + a1.w + a2.w + a3.w) * dn + bb.w);
    __half2 o0 = __floats2half2_rn(rx, ry);
    __half2 o1 = __floats2half2_rn(rz, rw);
    uint2 ov = make_uint2(*(uint32_t*)&o0, *(uint32_t*)&o1);
    ((uint2*)g_h1rh)[node * 32 + lane] = ov;
}

__global__ void __launch_bounds__(256, 6) k_aggr2(const float* __restrict__ b2,
                                                  float* __restrict__ out) {
    int node = blockIdx.x * 8 + (threadIdx.x >> 5);
    if (node >= NN) return;
    int lane = threadIdx.x & 31;
    const uint32_t* hs = (const uint32_t*)g_hs2h;

    int cnt = g_cnt[node];
    float dn = rsqrtf((float)cnt + 1.0f);
    int m_total = min(cnt, CAP);
    int padded  = (m_total + 7) & ~7;

    float2 a0, a1, a2, a3;
    a0 = make_float2(0.f, 0.f);
    hacc2(a0, hs[node * 32 + lane]);                // self term
    a1 = a2 = a3 = make_float2(0.f, 0.f);

    const int* slots = g_slot + node * CAP;
    for (int base = 0; base < padded; base += 32) {
        int idx = base + lane;
        int s   = (idx < m_total) ? __ldg(&slots[idx]) : NN;   // zero row
        int m   = min(32, padded - base);
        for (int k = 0; k < m; k += 8) {
            int s0 = __shfl_sync(0xffffffffu, s, k);
            int s1 = __shfl_sync(0xffffffffu, s, k + 1);
            int s2 = __shfl_sync(0xffffffffu, s, k + 2);
            int s3 = __shfl_sync(0xffffffffu, s, k + 3);
            int s4 = __shfl_sync(0xffffffffu, s, k + 4);
            int s5 = __shfl_sync(0xffffffffu, s, k + 5);
            int s6 = __shfl_sync(0xffffffffu, s, k + 6);
            int s7 = __shfl_sync(0xffffffffu, s, k + 7);
            uint32_t v0 = hs[s0 * 32 + lane];
            uint32_t v1 = hs[s1 * 32 + lane];
            uint32_t v2 = hs[s2 * 32 + lane];
            uint32_t v3 = hs[s3 * 32 + lane];
            uint32_t v4 = hs[s4 * 32 + lane];
            uint32_t v5 = hs[s5 * 32 + lane];
            uint32_t v6 = hs[s6 * 32 + lane];
            uint32_t v7 = hs[s7 * 32 + lane];
            __half2 p0 = __hadd2(h2(v0), h2(v1));
            __half2 p1 = __hadd2(h2(v2), h2(v3));
            __half2 p2 = __hadd2(h2(v4), h2(v5));
            __half2 p3 = __hadd2(h2(v6), h2(v7));
            hacc2p(a0, p0); hacc2p(a1, p1); hacc2p(a2, p2); hacc2p(a3, p3);
        }
    }
    float2 bb = ((const float2*)b2)[lane];
    float2 r;
    r.x = (a0.x + a1.x + a2.x + a3.x) * dn + bb.x;
    r.y = (a0.y + a1.y + a2.y + a3.y) * dn + bb.y;
    ((float2*)out)[node * 32 + lane] = r;
}

// ---------------- launch ----------------
extern "C" void kernel_launch(void* const* d_in, const int* in_sizes, int n_in,
                              void* d_out, int out_size) {
    const float* x  = (const float*)d_in[0];
    const void*  ei = d_in[1];
    const float* W1 = (const float*)d_in[2];
    const float* b1 = (const float*)d_in[3];
    const float* W2 = (const float*)d_in[4];
    const float* b2 = (const float*)d_in[5];
    const int E = in_sizes[1] / 2;

    constexpr int SM1 = (64 * 68 + DH   * 68) * 4;   // 52224 B
    constexpr int SM2 = (64 * 68 + DOUT * 68) * 4;   // 34816 B
    cudaFuncSetAttribute(k_gemm_h<DH, 1>,
                         cudaFuncAttributeMaxDynamicSharedMemorySize, SM1);
    cudaFuncSetAttribute(k_gemm_h<DOUT, 2>,
                         cudaFuncAttributeMaxDynamicSharedMemorySize, SM2);

    k_init     <<<NB, 256>>>((const int*)ei);
    k_countfill<<<(E + 255) / 256, 256>>>(ei, E);

    // Layer 1
    k_gemm_h<DH, 1><<<NN / 64, 256, SM1>>>(x, W1);
    k_aggr1<<<(NN + 7) / 8, 256>>>(b1);

    // Layer 2
    k_gemm_h<DOUT, 2><<<NN / 64, 256, SM2>>>(nullptr, W2);
    k_aggr2<<<(NN + 7) / 8, 256>>>(b2, (float*)d_out);
}